// round 10
// baseline (speedup 1.0000x reference)
#include <cuda_runtime.h>

#define SRC_N   128
#define PTS_N   2048
#define MIR_N   64
#define NCYL    16
#define NBOX    8
#define IMG_H   512
#define IMG_W   512
#define EXTENTF 12.0f
#define EPSF    1e-9f

#define TPB     256
#define PCHUNK  512                           // points per block
#define SGRP    4                             // sources per block
#define RPS     (PCHUNK / TPB)                // rays per thread per source = 2
#define NRAY    (2 * RPS)                     // rays in flight (2 sources x 2 pts)
#define NPTS_TOTAL (MIR_N * PTS_N)            // 131,072
#define NBLOCKS (MIR_N * (PTS_N / PCHUNK) * (SRC_N / SGRP))   // 8192

// Pixel mapping: fx = (qx + EXTENT) * W/(2*EXTENT) = qx*PXS + PXB
#define PXS  ((float)IMG_W / (2.0f * EXTENTF))
#define PXB  ((float)IMG_W / 2.0f)

// Conservative mirror-footprint radius (exact bound 0.84853) + margin.
#define RMIR    0.87f
#define RMARG   0.02f

struct CylS { float px, py, pz, ax, ay, az, L, r2; };

// Precomputed transformed points/normals. tp.w = (sp - tp) . sn  (plane numerator)
__device__ float4 g_tp[NPTS_TOTAL];
__device__ float4 g_tn[NPTS_TOTAL];

// ---------------------------------------------------------------------------
// Pre-pass: transform mirror points/normals; fold plane numerator into tp.w.
// ---------------------------------------------------------------------------
__global__ __launch_bounds__(TPB)
void transform_kernel(const float* __restrict__ mpts,
                      const float* __restrict__ mnrm,
                      const float* __restrict__ mpos,
                      const float* __restrict__ mrot,
                      const float* __restrict__ spos,
                      const float* __restrict__ snrm)
{
    const int idx = blockIdx.x * TPB + threadIdx.x;
    if (idx >= NPTS_TOTAL) return;
    const int m = idx >> 11;
    const float* Rm = mrot + m * 9;
    const float r00 = __ldg(Rm + 0), r01 = __ldg(Rm + 1), r02 = __ldg(Rm + 2);
    const float r10 = __ldg(Rm + 3), r11 = __ldg(Rm + 4), r12 = __ldg(Rm + 5);
    const float r20 = __ldg(Rm + 6), r21 = __ldg(Rm + 7), r22 = __ldg(Rm + 8);
    const float posx = __ldg(mpos + m * 3 + 0);
    const float posy = __ldg(mpos + m * 3 + 1);
    const float posz = __ldg(mpos + m * 3 + 2);

    const float ppx = __ldg(mpts + idx * 3 + 0);
    const float ppy = __ldg(mpts + idx * 3 + 1);
    const float ppz = __ldg(mpts + idx * 3 + 2);
    const float nnx = __ldg(mnrm + idx * 3 + 0);
    const float nny = __ldg(mnrm + idx * 3 + 1);
    const float nnz = __ldg(mnrm + idx * 3 + 2);

    const float snx = __ldg(snrm + 0), sny = __ldg(snrm + 1), snz = __ldg(snrm + 2);
    const float sp0 = __ldg(spos + 0), sp1 = __ldg(spos + 1), sp2 = __ldg(spos + 2);

    float4 tp, tn;
    tp.x = r00 * ppx + r01 * ppy + r02 * ppz + posx;
    tp.y = r10 * ppx + r11 * ppy + r12 * ppz + posy;
    tp.z = r20 * ppx + r21 * ppy + r22 * ppz + posz;
    tp.w = (sp0 - tp.x) * snx + (sp1 - tp.y) * sny + (sp2 - tp.z) * snz;
    tn.x = r00 * nnx + r01 * nny + r02 * nnz;
    tn.y = r10 * nnx + r11 * nny + r12 * nnz;
    tn.z = r20 * nnx + r21 * nny + r22 * nnz;
    tn.w = 0.0f;
    g_tp[idx] = tp;
    g_tn[idx] = tn;
}

// ---------------------------------------------------------------------------
// Render: block = (mirror m, 512-point chunk, 4 sources).
// Points staged in smem once, reused across sources. Source loop unrolled x2
// -> 4 independent ray chains per thread for latency hiding.
// ---------------------------------------------------------------------------
__global__ __launch_bounds__(TPB, 5)
void render_kernel(
    const float* __restrict__ sources,
    const float* __restrict__ mpos,
    const float* __restrict__ cyl_p1,
    const float* __restrict__ cyl_p2,
    const float* __restrict__ cyl_r,
    const float* __restrict__ box_p1,
    const float* __restrict__ box_p2,
    const float* __restrict__ snrm,
    float* __restrict__ img)
{
    __shared__ float4 s_tp[PCHUNK];           // 8 KB
    __shared__ float4 s_tn[PCHUNK];           // 8 KB
    __shared__ float4 scraw[NCYL];            // (px,py,pz,r2)
    __shared__ float  scrawL[NCYL];
    __shared__ float  scrawTopZ[NCYL];
    __shared__ int    svert[NCYL];
    __shared__ CylS   scg[NCYL];
    __shared__ float4 sbrawA[NBOX];           // (ax,ay,az,bx)
    __shared__ float4 sbrawB[NBOX];           // (by,bz,bcx,bcy)
    __shared__ float  sbrawR[NBOX];
    __shared__ unsigned char sflag[SGRP][NCYL + NBOX];
    __shared__ float4 scylS[SGRP][NCYL];
    __shared__ float  scylLS[SGRP][NCYL];
    __shared__ float4 sbAS[SGRP][NBOX];
    __shared__ float4 sbBS[SGRP][NBOX];
    __shared__ int    s_ncyl[SGRP], s_nbox[SGRP];
    __shared__ int    s_allz;
    __shared__ float  ssn[3];

    const int tid = threadIdx.x;
    const int b   = blockIdx.x;
    const int m   = b >> 7;                   // 128 inner blocks per mirror
    const int rem = b & 127;
    const int pc  = rem >> 5;                 // point chunk 0..3
    const int sg  = rem & 31;                 // source group 0..31
    const int pbase = pc * PCHUNK;
    const int sbase = sg * SGRP;

    // ---- Stage A: stage 512 points into smem ----
    const int gb = m * PTS_N + pbase;
    #pragma unroll
    for (int k = 0; k < PCHUNK / TPB; ++k) {
        const int i = k * TPB + tid;
        s_tp[i] = __ldg(&g_tp[gb + i]);
        s_tn[i] = __ldg(&g_tn[gb + i]);
    }

    // ---- Stage B0: reduce occluder raw data ----
    if (tid < NCYL) {
        const float p1x = cyl_p1[tid * 3 + 0];
        const float p1y = cyl_p1[tid * 3 + 1];
        const float p1z = cyl_p1[tid * 3 + 2];
        float axx = cyl_p2[tid * 3 + 0] - p1x;
        float axy = cyl_p2[tid * 3 + 1] - p1y;
        float axz = cyl_p2[tid * 3 + 2] - p1z;
        const float L  = sqrtf(axx * axx + axy * axy + axz * axz);
        const float il = __fdividef(1.0f, L + EPSF);
        const float uax = axx * il, uay = axy * il, uaz = axz * il;
        const float r = cyl_r[tid];
        scraw[tid]    = make_float4(p1x, p1y, p1z, r * r);
        scrawL[tid]   = L;
        scrawTopZ[tid]= p1z + axz;
        svert[tid]    = (uax == 0.0f && uay == 0.0f && uaz > 0.0f) ? 1 : 0;
        CylS c; c.px = p1x; c.py = p1y; c.pz = p1z;
        c.ax = uax; c.ay = uay; c.az = uaz; c.L = L; c.r2 = r * r;
        scg[tid] = c;
    } else if (tid < NCYL + NBOX) {
        const int bb = tid - NCYL;
        const float ax = box_p1[bb * 3 + 0], ay = box_p1[bb * 3 + 1], az = box_p1[bb * 3 + 2];
        const float bx = box_p2[bb * 3 + 0], by = box_p2[bb * 3 + 1], bz = box_p2[bb * 3 + 2];
        sbrawA[bb] = make_float4(ax, ay, az, bx);
        sbrawB[bb] = make_float4(by, bz, 0.5f * (ax + bx), 0.5f * (ay + by));
        sbrawR[bb] = 0.5f * sqrtf((bx - ax) * (bx - ax) + (by - ay) * (by - ay));
    } else if (tid < NCYL + NBOX + 3) {
        ssn[tid - NCYL - NBOX] = snrm[tid - NCYL - NBOX];
    }
    __syncthreads();

    // ---- Stage B1: per-(source, occluder) culls in parallel ----
    if (tid < SGRP * (NCYL + NBOX)) {
        const int j = tid / (NCYL + NBOX);
        const int o = tid % (NCYL + NBOX);
        const int si = sbase + j;
        const float sx = __ldg(sources + si * 3 + 0);
        const float sy = __ldg(sources + si * 3 + 1);
        const float szz = __ldg(sources + si * 3 + 2);
        const float cx = __ldg(mpos + m * 3 + 0);
        const float cy = __ldg(mpos + m * 3 + 1);
        const float mz = __ldg(mpos + m * 3 + 2);
        const float cxs = cx - sx, cys = cy - sy;
        const float dcs = sqrtf(cxs * cxs + cys * cys);

        int cull;
        if (o < NCYL) {
            const float4 cr = scraw[o];
            const float r = sqrtf(cr.w);
            const float qxs = cr.x - sx, qys = cr.y - sy;
            const float crs = fabsf(qxs * cys - qys * cxs);
            const float dqs = sqrtf(qxs * qxs + qys * qys);
            cull = (crs - dqs * RMIR) > (r + RMARG) * (dcs + RMIR);
            if (svert[o]) {
                const float den = szz - (mz + RMIR);
                if (den > 0.0f) {
                    const float num = scrawTopZ[o] - (mz - RMIR);
                    const float dmcx = cr.x - cx, dmcy = cr.y - cy;
                    const float dmc = sqrtf(dmcx * dmcx + dmcy * dmcy);
                    if (num <= 0.0f) cull = 1;
                    else {
                        const float reach = __fdividef(num, den) * (dcs + RMIR);
                        if (dmc - r - RMARG > RMIR + reach) cull = 1;
                    }
                }
            }
        } else {
            const int bb = o - NCYL;
            const float4 A = sbrawA[bb];
            const float4 B = sbrawB[bb];
            const float reff = sbrawR[bb];
            const float bcx = B.z, bcy = B.w;
            const float qxs = bcx - sx, qys = bcy - sy;
            const float crs = fabsf(qxs * cys - qys * cxs);
            const float dqs = sqrtf(qxs * qxs + qys * qys);
            cull = (crs - dqs * RMIR) > (reff + RMARG) * (dcs + RMIR);
            const float den = szz - (mz + RMIR);
            if (den > 0.0f) {
                const float zmax = fmaxf(A.z, B.y);
                const float num = zmax - (mz - RMIR);
                const float dmcx = bcx - cx, dmcy = bcy - cy;
                const float dmc = sqrtf(dmcx * dmcx + dmcy * dmcy);
                if (num <= 0.0f) cull = 1;
                else {
                    const float reach = __fdividef(num, den) * (dcs + RMIR);
                    if (dmc - reff - RMARG > RMIR + reach) cull = 1;
                }
            }
        }
        sflag[j][o] = (unsigned char)(!cull);
    }
    __syncthreads();

    // ---- Stage C: per-source compaction + allz ----
    if (tid < SGRP) {
        const int j = tid;
        int n = 0;
        for (int c = 0; c < NCYL; ++c) {
            if (sflag[j][c]) { scylS[j][n] = scraw[c]; scylLS[j][n] = scrawL[c]; ++n; }
        }
        s_ncyl[j] = n;
        int nb = 0;
        for (int bb = 0; bb < NBOX; ++bb) {
            if (sflag[j][NCYL + bb]) { sbAS[j][nb] = sbrawA[bb]; sbBS[j][nb] = sbrawB[bb]; ++nb; }
        }
        s_nbox[j] = nb;
    } else if (tid == SGRP) {
        int allz = 1;
        #pragma unroll
        for (int c = 0; c < NCYL; ++c) allz &= svert[c];
        s_allz = allz;
    }
    __syncthreads();

    const float snx = ssn[0], sny = ssn[1], snz = ssn[2];
    const int allz = s_allz;

    // ---- Stage D: 2 sources per iteration x 2 points = 4 ray chains ----
    #pragma unroll
    for (int jj = 0; jj < SGRP; jj += 2) {
        float SXA[2], SYA[2], SZA[2];
        #pragma unroll
        for (int q = 0; q < 2; ++q) {
            const int si = sbase + jj + q;
            SXA[q] = __ldg(sources + si * 3 + 0);
            SYA[q] = __ldg(sources + si * 3 + 1);
            SZA[q] = __ldg(sources + si * 3 + 2);
        }

        float TPX[NRAY], TPY[NRAY], TPZ[NRAY];
        float UX[NRAY], UY[NRAY], UZ[NRAY];
        float VAL[NRAY];
        int   PIX[NRAY];

        #pragma unroll
        for (int r = 0; r < NRAY; ++r) {
            const int q = r >> 1;                    // local source 0/1
            const int i = (r & 1) * TPB + tid;       // point index
            const float4 tp4 = s_tp[i];
            const float4 tn4 = s_tn[i];
            const float tpx = tp4.x, tpy = tp4.y, tpz = tp4.z;
            const float tnum = tp4.w;                // precomputed plane numerator

            const float Dx = tpx - SXA[q], Dy = tpy - SYA[q], Dz = tpz - SZA[q];
            const float dnU = Dx * tn4.x + Dy * tn4.y + Dz * tn4.z;

            const float rlx = Dx - 2.0f * dnU * tn4.x;
            const float rly = Dy - 2.0f * dnU * tn4.y;
            const float rlz = Dz - 2.0f * dnU * tn4.z;
            const float denom = rlx * snx + rly * sny + rlz * snz;
            const float t = __fdividef(tnum, denom + EPSF);
            const float qx = fmaf(t, rlx, tpx);
            const float qy = fmaf(t, rly, tpy);
            const float fx = fmaf(qx, PXS, PXB);
            const float fy = fmaf(qy, PXS, PXB);
            const int ix = (int)floorf(fx);
            const int iy = (int)floorf(fy);
            const bool ok = ((unsigned)ix < IMG_W) & ((unsigned)iy < IMG_H);

            const float dd = Dx * Dx + Dy * Dy + Dz * Dz;
            PIX[r] = iy * IMG_W + ix;
            VAL[r] = ok ? fabsf(dnU) * rsqrtf(dd) : 0.0f;
            TPX[r] = tpx; TPY[r] = tpy; TPZ[r] = tpz;
            UX[r] = -Dx; UY[r] = -Dy; UZ[r] = -Dz;
        }

        #pragma unroll
        for (int r = 0; r < NRAY; ++r) {
            if (VAL[r] == 0.0f) continue;
            const int j = jj + (r >> 1);
            const int ncyl = s_ncyl[j];
            const int nbox = s_nbox[j];
            const float tpx = TPX[r], tpy = TPY[r], tpz = TPZ[r];
            const float ux = UX[r], uy = UY[r], uz = UZ[r];
            bool hit = false;

            if (nbox > 0) {
                const float dux = (fabsf(ux) < EPSF) ? EPSF : ux;
                const float duy = (fabsf(uy) < EPSF) ? EPSF : uy;
                const float duz = (fabsf(uz) < EPSF) ? EPSF : uz;
                const float ivx = __fdividef(1.0f, dux);
                const float ivy = __fdividef(1.0f, duy);
                const float ivz = __fdividef(1.0f, duz);
                const float ox = tpx * ivx, oy = tpy * ivy, oz = tpz * ivz;
                for (int bb = 0; bb < nbox; ++bb) {
                    const float4 A = sbAS[j][bb];
                    const float4 B = sbBS[j][bb];
                    const float t1x = fmaf(A.x, ivx, -ox);
                    const float t2x = fmaf(A.w, ivx, -ox);
                    const float t1y = fmaf(A.y, ivy, -oy);
                    const float t2y = fmaf(B.x, ivy, -oy);
                    const float t1z = fmaf(A.z, ivz, -oz);
                    const float t2z = fmaf(B.y, ivz, -oz);
                    const float tmin = fmaxf(fmaxf(fminf(t1x, t2x), fminf(t1y, t2y)), fminf(t1z, t2z));
                    const float tmax = fminf(fminf(fmaxf(t1x, t2x), fmaxf(t1y, t2y)), fmaxf(t1z, t2z));
                    if (tmax >= fmaxf(tmin, EPSF)) { hit = true; break; }
                }
            }

            if (!hit) {
                if (allz) {
                    if (ncyl > 0) {
                        const float A2  = ux * ux + uy * uy;
                        const float i2a = __fdividef(1.0f, A2 + EPSF);
                        for (int c = 0; c < ncyl; ++c) {
                            const float4 cc = scylS[j][c];
                            const float mx = tpx - cc.x;
                            const float my = tpy - cc.y;
                            const float Bh = mx * ux + my * uy;
                            const float C  = fmaf(mx, mx, my * my) - cc.w;
                            const float d4 = fmaf(Bh, Bh, -A2 * C);
                            if (d4 > 0.0f) {
                                const float sq = sqrtf(d4);
                                const float t1 = (-Bh - sq) * i2a;
                                const float t2 = (-Bh + sq) * i2a;
                                const float oa = tpz - cc.z;
                                const float a1 = fmaf(t1, uz, oa);
                                const float a2 = fmaf(t2, uz, oa);
                                const float L  = scylLS[j][c];
                                const bool h1 = (t1 > EPSF) & (a1 >= 0.0f) & (a1 <= L);
                                const bool h2 = (t2 > EPSF) & (a2 >= 0.0f) & (a2 <= L);
                                if (h1 | h2) { hit = true; break; }
                            }
                        }
                    }
                } else {
                    const float uu = ux * ux + uy * uy + uz * uz;
                    for (int c = 0; c < NCYL; ++c) {
                        const CylS cc = scg[c];
                        const float ocx = tpx - cc.px;
                        const float ocy = tpy - cc.py;
                        const float ocz = tpz - cc.pz;
                        const float ua  = ux * cc.ax + uy * cc.ay + uz * cc.az;
                        const float oa  = ocx * cc.ax + ocy * cc.ay + ocz * cc.az;
                        const float ocu = ocx * ux + ocy * uy + ocz * uz;
                        const float oc2 = ocx * ocx + ocy * ocy + ocz * ocz;
                        const float A   = uu - ua * ua;
                        const float Bh  = ocu - oa * ua;
                        const float C   = oc2 - oa * oa - cc.r2;
                        const float d4  = fmaf(Bh, Bh, -A * C);
                        if (d4 > 0.0f) {
                            const float sq  = sqrtf(d4);
                            const float i2a = __fdividef(1.0f, A + EPSF);
                            const float t1  = (-Bh - sq) * i2a;
                            const float t2  = (-Bh + sq) * i2a;
                            const float a1  = fmaf(t1, ua, oa);
                            const float a2  = fmaf(t2, ua, oa);
                            const bool h1 = (t1 > EPSF) & (a1 >= 0.0f) & (a1 <= cc.L);
                            const bool h2 = (t2 > EPSF) & (a2 >= 0.0f) & (a2 <= cc.L);
                            if (h1 | h2) { hit = true; break; }
                        }
                    }
                }
            }

            if (!hit) atomicAdd(&img[PIX[r]], VAL[r]);
        }
    }
}

extern "C" void kernel_launch(void* const* d_in, const int* in_sizes, int n_in,
                              void* d_out, int out_size) {
    const float* sources = (const float*)d_in[0];
    const float* mpts    = (const float*)d_in[1];
    const float* mnrm    = (const float*)d_in[2];
    const float* mpos    = (const float*)d_in[3];
    const float* mrot    = (const float*)d_in[4];
    const float* cyl_p1  = (const float*)d_in[5];
    const float* cyl_p2  = (const float*)d_in[6];
    const float* cyl_r   = (const float*)d_in[7];
    const float* box_p1  = (const float*)d_in[8];
    const float* box_p2  = (const float*)d_in[9];
    const float* spos    = (const float*)d_in[10];
    const float* snrm    = (const float*)d_in[11];
    float* img = (float*)d_out;

    cudaMemsetAsync(img, 0, (size_t)out_size * sizeof(float), 0);

    transform_kernel<<<NPTS_TOTAL / TPB, TPB>>>(mpts, mnrm, mpos, mrot, spos, snrm);

    render_kernel<<<NBLOCKS, TPB>>>(sources, mpos,
                                    cyl_p1, cyl_p2, cyl_r,
                                    box_p1, box_p2,
                                    snrm, img);
}

// round 11
// speedup vs baseline: 1.1043x; 1.1043x over previous
#include <cuda_runtime.h>

#define SRC_N   128
#define PTS_N   2048
#define MIR_N   64
#define NCYL    16
#define NBOX    8
#define IMG_H   512
#define IMG_W   512
#define EXTENTF 12.0f
#define EPSF    1e-9f

#define TPB     256
#define PCHUNK  512                           // points per block
#define SGRP    8                             // sources per block
#define RPS     (PCHUNK / TPB)                // rays per thread per source = 2
#define NPTS_TOTAL (MIR_N * PTS_N)            // 131,072
#define NBLOCKS (MIR_N * (PTS_N / PCHUNK) * (SRC_N / SGRP))   // 4096

// Pixel mapping: fx = (qx + EXTENT) * W/(2*EXTENT) = qx*PXS + PXB
#define PXS  ((float)IMG_W / (2.0f * EXTENTF))
#define PXB  ((float)IMG_W / 2.0f)

// Conservative mirror-footprint radius (exact bound 0.84853) + margin.
#define RMIR    0.87f
#define RMARG   0.02f

struct CylS { float px, py, pz, ax, ay, az, L, r2; };

// Precomputed transformed points/normals. tp.w = (sp - tp) . sn  (plane numerator)
__device__ float4 g_tp[NPTS_TOTAL];
__device__ float4 g_tn[NPTS_TOTAL];

// ---------------------------------------------------------------------------
// Pre-pass: transform mirror points/normals; fold plane numerator into tp.w.
// ---------------------------------------------------------------------------
__global__ __launch_bounds__(TPB)
void transform_kernel(const float* __restrict__ mpts,
                      const float* __restrict__ mnrm,
                      const float* __restrict__ mpos,
                      const float* __restrict__ mrot,
                      const float* __restrict__ spos,
                      const float* __restrict__ snrm)
{
    const int idx = blockIdx.x * TPB + threadIdx.x;
    if (idx >= NPTS_TOTAL) return;
    const int m = idx >> 11;
    const float* Rm = mrot + m * 9;
    const float r00 = __ldg(Rm + 0), r01 = __ldg(Rm + 1), r02 = __ldg(Rm + 2);
    const float r10 = __ldg(Rm + 3), r11 = __ldg(Rm + 4), r12 = __ldg(Rm + 5);
    const float r20 = __ldg(Rm + 6), r21 = __ldg(Rm + 7), r22 = __ldg(Rm + 8);
    const float posx = __ldg(mpos + m * 3 + 0);
    const float posy = __ldg(mpos + m * 3 + 1);
    const float posz = __ldg(mpos + m * 3 + 2);

    const float ppx = __ldg(mpts + idx * 3 + 0);
    const float ppy = __ldg(mpts + idx * 3 + 1);
    const float ppz = __ldg(mpts + idx * 3 + 2);
    const float nnx = __ldg(mnrm + idx * 3 + 0);
    const float nny = __ldg(mnrm + idx * 3 + 1);
    const float nnz = __ldg(mnrm + idx * 3 + 2);

    const float snx = __ldg(snrm + 0), sny = __ldg(snrm + 1), snz = __ldg(snrm + 2);
    const float sp0 = __ldg(spos + 0), sp1 = __ldg(spos + 1), sp2 = __ldg(spos + 2);

    float4 tp, tn;
    tp.x = r00 * ppx + r01 * ppy + r02 * ppz + posx;
    tp.y = r10 * ppx + r11 * ppy + r12 * ppz + posy;
    tp.z = r20 * ppx + r21 * ppy + r22 * ppz + posz;
    tp.w = (sp0 - tp.x) * snx + (sp1 - tp.y) * sny + (sp2 - tp.z) * snz;
    tn.x = r00 * nnx + r01 * nny + r02 * nnz;
    tn.y = r10 * nnx + r11 * nny + r12 * nnz;
    tn.z = r20 * nnx + r21 * nny + r22 * nnz;
    tn.w = 0.0f;
    g_tp[idx] = tp;
    g_tn[idx] = tn;
}

// ---------------------------------------------------------------------------
// Stage D worker: loop over SGRP sources, 2 rays/thread each.
// SZN = sensor normal is exactly (0,0,1) (block-uniform specialization).
// ---------------------------------------------------------------------------
template<bool SZN>
__device__ __forceinline__ void stage_d(
    const int tid, const int sbase, const int allz,
    const float4* __restrict__ s_tp, const float4* __restrict__ s_tn,
    const float* __restrict__ sources,
    const float4 (* __restrict__ scylS)[NCYL], const float (* __restrict__ scylLS)[NCYL],
    const float4 (* __restrict__ sbAS)[NBOX],  const float4 (* __restrict__ sbBS)[NBOX],
    const int* __restrict__ s_ncyl, const int* __restrict__ s_nbox,
    const CylS* __restrict__ scg,
    const float snx, const float sny, const float snz,
    float* __restrict__ img)
{
    for (int j = 0; j < SGRP; ++j) {
        const int si = sbase + j;
        const float sx = __ldg(sources + si * 3 + 0);
        const float sy = __ldg(sources + si * 3 + 1);
        const float sz = __ldg(sources + si * 3 + 2);
        const int ncyl = s_ncyl[j];
        const int nbox = s_nbox[j];

        float TPX[RPS], TPY[RPS], TPZ[RPS];
        float UX[RPS], UY[RPS], UZ[RPS];
        float VAL[RPS];
        int   PIX[RPS];

        #pragma unroll
        for (int r = 0; r < RPS; ++r) {
            const int i = r * TPB + tid;
            const float4 tp4 = s_tp[i];
            const float4 tn4 = s_tn[i];
            const float tpx = tp4.x, tpy = tp4.y, tpz = tp4.z;
            const float tnum = tp4.w;

            const float Dx = tpx - sx, Dy = tpy - sy, Dz = tpz - sz;
            const float dnU = Dx * tn4.x + Dy * tn4.y + Dz * tn4.z;

            const float rlx = Dx - 2.0f * dnU * tn4.x;
            const float rly = Dy - 2.0f * dnU * tn4.y;
            const float rlz = Dz - 2.0f * dnU * tn4.z;
            float denom;
            if (SZN) denom = rlz;
            else     denom = rlx * snx + rly * sny + rlz * snz;
            const float t = __fdividef(tnum, denom + EPSF);
            const float qx = fmaf(t, rlx, tpx);
            const float qy = fmaf(t, rly, tpy);
            const float fx = fmaf(qx, PXS, PXB);
            const float fy = fmaf(qy, PXS, PXB);
            const int ix = (int)floorf(fx);
            const int iy = (int)floorf(fy);
            const bool ok = ((unsigned)ix < IMG_W) & ((unsigned)iy < IMG_H);

            const float dd = Dx * Dx + Dy * Dy + Dz * Dz;
            PIX[r] = iy * IMG_W + ix;
            VAL[r] = ok ? fabsf(dnU) * rsqrtf(dd) : 0.0f;
            TPX[r] = tpx; TPY[r] = tpy; TPZ[r] = tpz;
            UX[r] = -Dx; UY[r] = -Dy; UZ[r] = -Dz;
        }

        #pragma unroll
        for (int r = 0; r < RPS; ++r) {
            if (VAL[r] == 0.0f) continue;
            const float tpx = TPX[r], tpy = TPY[r], tpz = TPZ[r];
            const float ux = UX[r], uy = UY[r], uz = UZ[r];
            bool hit = false;

            if (nbox > 0) {
                const float dux = (fabsf(ux) < EPSF) ? EPSF : ux;
                const float duy = (fabsf(uy) < EPSF) ? EPSF : uy;
                const float duz = (fabsf(uz) < EPSF) ? EPSF : uz;
                const float ivx = __fdividef(1.0f, dux);
                const float ivy = __fdividef(1.0f, duy);
                const float ivz = __fdividef(1.0f, duz);
                const float ox = tpx * ivx, oy = tpy * ivy, oz = tpz * ivz;
                for (int bb = 0; bb < nbox; ++bb) {
                    const float4 A = sbAS[j][bb];
                    const float4 B = sbBS[j][bb];
                    const float t1x = fmaf(A.x, ivx, -ox);
                    const float t2x = fmaf(A.w, ivx, -ox);
                    const float t1y = fmaf(A.y, ivy, -oy);
                    const float t2y = fmaf(B.x, ivy, -oy);
                    const float t1z = fmaf(A.z, ivz, -oz);
                    const float t2z = fmaf(B.y, ivz, -oz);
                    const float tmin = fmaxf(fmaxf(fminf(t1x, t2x), fminf(t1y, t2y)), fminf(t1z, t2z));
                    const float tmax = fminf(fminf(fmaxf(t1x, t2x), fmaxf(t1y, t2y)), fmaxf(t1z, t2z));
                    if (tmax >= fmaxf(tmin, EPSF)) { hit = true; break; }
                }
            }

            if (!hit) {
                if (allz) {
                    if (ncyl > 0) {
                        const float A2  = ux * ux + uy * uy;
                        const float i2a = __fdividef(1.0f, A2 + EPSF);
                        for (int c = 0; c < ncyl; ++c) {
                            const float4 cc = scylS[j][c];
                            const float mx = tpx - cc.x;
                            const float my = tpy - cc.y;
                            const float Bh = mx * ux + my * uy;
                            const float C  = fmaf(mx, mx, my * my) - cc.w;
                            const float d4 = fmaf(Bh, Bh, -A2 * C);
                            if (d4 > 0.0f) {
                                const float sq = sqrtf(d4);
                                const float t1 = (-Bh - sq) * i2a;
                                const float t2 = (-Bh + sq) * i2a;
                                const float oa = tpz - cc.z;
                                const float a1 = fmaf(t1, uz, oa);
                                const float a2 = fmaf(t2, uz, oa);
                                const float L  = scylLS[j][c];
                                const bool h1 = (t1 > EPSF) & (a1 >= 0.0f) & (a1 <= L);
                                const bool h2 = (t2 > EPSF) & (a2 >= 0.0f) & (a2 <= L);
                                if (h1 | h2) { hit = true; break; }
                            }
                        }
                    }
                } else {
                    const float uu = ux * ux + uy * uy + uz * uz;
                    for (int c = 0; c < NCYL; ++c) {
                        const CylS cc = scg[c];
                        const float ocx = tpx - cc.px;
                        const float ocy = tpy - cc.py;
                        const float ocz = tpz - cc.pz;
                        const float ua  = ux * cc.ax + uy * cc.ay + uz * cc.az;
                        const float oa  = ocx * cc.ax + ocy * cc.ay + ocz * cc.az;
                        const float ocu = ocx * ux + ocy * uy + ocz * uz;
                        const float oc2 = ocx * ocx + ocy * ocy + ocz * ocz;
                        const float A   = uu - ua * ua;
                        const float Bh  = ocu - oa * ua;
                        const float C   = oc2 - oa * oa - cc.r2;
                        const float d4  = fmaf(Bh, Bh, -A * C);
                        if (d4 > 0.0f) {
                            const float sq  = sqrtf(d4);
                            const float i2a = __fdividef(1.0f, A + EPSF);
                            const float t1  = (-Bh - sq) * i2a;
                            const float t2  = (-Bh + sq) * i2a;
                            const float a1  = fmaf(t1, ua, oa);
                            const float a2  = fmaf(t2, ua, oa);
                            const bool h1 = (t1 > EPSF) & (a1 >= 0.0f) & (a1 <= cc.L);
                            const bool h2 = (t2 > EPSF) & (a2 >= 0.0f) & (a2 <= cc.L);
                            if (h1 | h2) { hit = true; break; }
                        }
                    }
                }
            }

            if (!hit) atomicAdd(&img[PIX[r]], VAL[r]);
        }
    }
}

// ---------------------------------------------------------------------------
// Render: block = (mirror m, 512-point chunk, 8 sources). R9 structure.
// ---------------------------------------------------------------------------
__global__ __launch_bounds__(TPB, 6)
void render_kernel(
    const float* __restrict__ sources,
    const float* __restrict__ mpos,
    const float* __restrict__ cyl_p1,
    const float* __restrict__ cyl_p2,
    const float* __restrict__ cyl_r,
    const float* __restrict__ box_p1,
    const float* __restrict__ box_p2,
    const float* __restrict__ snrm,
    float* __restrict__ img)
{
    __shared__ float4 s_tp[PCHUNK];           // 8 KB
    __shared__ float4 s_tn[PCHUNK];           // 8 KB
    __shared__ float4 scraw[NCYL];
    __shared__ float  scrawL[NCYL];
    __shared__ float  scrawTopZ[NCYL];
    __shared__ int    svert[NCYL];
    __shared__ CylS   scg[NCYL];
    __shared__ float4 sbrawA[NBOX];
    __shared__ float4 sbrawB[NBOX];
    __shared__ float  sbrawR[NBOX];
    __shared__ unsigned char sflag[SGRP][NCYL + NBOX];
    __shared__ float4 scylS[SGRP][NCYL];
    __shared__ float  scylLS[SGRP][NCYL];
    __shared__ float4 sbAS[SGRP][NBOX];
    __shared__ float4 sbBS[SGRP][NBOX];
    __shared__ int    s_ncyl[SGRP], s_nbox[SGRP];
    __shared__ int    s_allz;
    __shared__ float  ssn[3];

    const int tid = threadIdx.x;
    const int b   = blockIdx.x;
    const int m   = b >> 6;                   // 64 inner blocks per mirror
    const int rem = b & 63;
    const int pc  = rem >> 4;                 // point chunk 0..3
    const int sg  = rem & 15;                 // source group 0..15
    const int pbase = pc * PCHUNK;
    const int sbase = sg * SGRP;

    // ---- Stage A: stage 512 points into smem ----
    const int gb = m * PTS_N + pbase;
    #pragma unroll
    for (int k = 0; k < PCHUNK / TPB; ++k) {
        const int i = k * TPB + tid;
        s_tp[i] = __ldg(&g_tp[gb + i]);
        s_tn[i] = __ldg(&g_tn[gb + i]);
    }

    // ---- Stage B0: reduce occluder raw data ----
    if (tid < NCYL) {
        const float p1x = cyl_p1[tid * 3 + 0];
        const float p1y = cyl_p1[tid * 3 + 1];
        const float p1z = cyl_p1[tid * 3 + 2];
        float axx = cyl_p2[tid * 3 + 0] - p1x;
        float axy = cyl_p2[tid * 3 + 1] - p1y;
        float axz = cyl_p2[tid * 3 + 2] - p1z;
        const float L  = sqrtf(axx * axx + axy * axy + axz * axz);
        const float il = __fdividef(1.0f, L + EPSF);
        const float uax = axx * il, uay = axy * il, uaz = axz * il;
        const float r = cyl_r[tid];
        scraw[tid]    = make_float4(p1x, p1y, p1z, r * r);
        scrawL[tid]   = L;
        scrawTopZ[tid]= p1z + axz;
        svert[tid]    = (uax == 0.0f && uay == 0.0f && uaz > 0.0f) ? 1 : 0;
        CylS c; c.px = p1x; c.py = p1y; c.pz = p1z;
        c.ax = uax; c.ay = uay; c.az = uaz; c.L = L; c.r2 = r * r;
        scg[tid] = c;
    } else if (tid < NCYL + NBOX) {
        const int bb = tid - NCYL;
        const float ax = box_p1[bb * 3 + 0], ay = box_p1[bb * 3 + 1], az = box_p1[bb * 3 + 2];
        const float bx = box_p2[bb * 3 + 0], by = box_p2[bb * 3 + 1], bz = box_p2[bb * 3 + 2];
        sbrawA[bb] = make_float4(ax, ay, az, bx);
        sbrawB[bb] = make_float4(by, bz, 0.5f * (ax + bx), 0.5f * (ay + by));
        sbrawR[bb] = 0.5f * sqrtf((bx - ax) * (bx - ax) + (by - ay) * (by - ay));
    } else if (tid < NCYL + NBOX + 3) {
        ssn[tid - NCYL - NBOX] = snrm[tid - NCYL - NBOX];
    }
    __syncthreads();

    // ---- Stage B1: per-(source, occluder) culls in parallel ----
    if (tid < SGRP * (NCYL + NBOX)) {
        const int j = tid / (NCYL + NBOX);
        const int o = tid % (NCYL + NBOX);
        const int si = sbase + j;
        const float sx = __ldg(sources + si * 3 + 0);
        const float sy = __ldg(sources + si * 3 + 1);
        const float szz = __ldg(sources + si * 3 + 2);
        const float cx = __ldg(mpos + m * 3 + 0);
        const float cy = __ldg(mpos + m * 3 + 1);
        const float mz = __ldg(mpos + m * 3 + 2);
        const float cxs = cx - sx, cys = cy - sy;
        const float dcs = sqrtf(cxs * cxs + cys * cys);

        int cull;
        if (o < NCYL) {
            const float4 cr = scraw[o];
            const float r = sqrtf(cr.w);
            const float qxs = cr.x - sx, qys = cr.y - sy;
            const float crs = fabsf(qxs * cys - qys * cxs);
            const float dqs = sqrtf(qxs * qxs + qys * qys);
            cull = (crs - dqs * RMIR) > (r + RMARG) * (dcs + RMIR);
            if (svert[o]) {
                const float den = szz - (mz + RMIR);
                if (den > 0.0f) {
                    const float num = scrawTopZ[o] - (mz - RMIR);
                    const float dmcx = cr.x - cx, dmcy = cr.y - cy;
                    const float dmc = sqrtf(dmcx * dmcx + dmcy * dmcy);
                    if (num <= 0.0f) cull = 1;
                    else {
                        const float reach = __fdividef(num, den) * (dcs + RMIR);
                        if (dmc - r - RMARG > RMIR + reach) cull = 1;
                    }
                }
            }
        } else {
            const int bb = o - NCYL;
            const float4 A = sbrawA[bb];
            const float4 B = sbrawB[bb];
            const float reff = sbrawR[bb];
            const float bcx = B.z, bcy = B.w;
            const float qxs = bcx - sx, qys = bcy - sy;
            const float crs = fabsf(qxs * cys - qys * cxs);
            const float dqs = sqrtf(qxs * qxs + qys * qys);
            cull = (crs - dqs * RMIR) > (reff + RMARG) * (dcs + RMIR);
            const float den = szz - (mz + RMIR);
            if (den > 0.0f) {
                const float zmax = fmaxf(A.z, B.y);
                const float num = zmax - (mz - RMIR);
                const float dmcx = bcx - cx, dmcy = bcy - cy;
                const float dmc = sqrtf(dmcx * dmcx + dmcy * dmcy);
                if (num <= 0.0f) cull = 1;
                else {
                    const float reach = __fdividef(num, den) * (dcs + RMIR);
                    if (dmc - reff - RMARG > RMIR + reach) cull = 1;
                }
            }
        }
        sflag[j][o] = (unsigned char)(!cull);
    }
    __syncthreads();

    // ---- Stage C: per-source compaction + allz ----
    if (tid < SGRP) {
        const int j = tid;
        int n = 0;
        for (int c = 0; c < NCYL; ++c) {
            if (sflag[j][c]) { scylS[j][n] = scraw[c]; scylLS[j][n] = scrawL[c]; ++n; }
        }
        s_ncyl[j] = n;
        int nb = 0;
        for (int bb = 0; bb < NBOX; ++bb) {
            if (sflag[j][NCYL + bb]) { sbAS[j][nb] = sbrawA[bb]; sbBS[j][nb] = sbrawB[bb]; ++nb; }
        }
        s_nbox[j] = nb;
    } else if (tid == SGRP) {
        int allz = 1;
        #pragma unroll
        for (int c = 0; c < NCYL; ++c) allz &= svert[c];
        s_allz = allz;
    }
    __syncthreads();

    const float snx = ssn[0], sny = ssn[1], snz = ssn[2];
    const int allz = s_allz;
    const bool szn = (snx == 0.0f) & (sny == 0.0f) & (snz == 1.0f);

    if (szn)
        stage_d<true>(tid, sbase, allz, s_tp, s_tn, sources,
                      scylS, scylLS, sbAS, sbBS, s_ncyl, s_nbox, scg,
                      snx, sny, snz, img);
    else
        stage_d<false>(tid, sbase, allz, s_tp, s_tn, sources,
                       scylS, scylLS, sbAS, sbBS, s_ncyl, s_nbox, scg,
                       snx, sny, snz, img);
}

extern "C" void kernel_launch(void* const* d_in, const int* in_sizes, int n_in,
                              void* d_out, int out_size) {
    const float* sources = (const float*)d_in[0];
    const float* mpts    = (const float*)d_in[1];
    const float* mnrm    = (const float*)d_in[2];
    const float* mpos    = (const float*)d_in[3];
    const float* mrot    = (const float*)d_in[4];
    const float* cyl_p1  = (const float*)d_in[5];
    const float* cyl_p2  = (const float*)d_in[6];
    const float* cyl_r   = (const float*)d_in[7];
    const float* box_p1  = (const float*)d_in[8];
    const float* box_p2  = (const float*)d_in[9];
    const float* spos    = (const float*)d_in[10];
    const float* snrm    = (const float*)d_in[11];
    float* img = (float*)d_out;

    cudaMemsetAsync(img, 0, (size_t)out_size * sizeof(float), 0);

    transform_kernel<<<NPTS_TOTAL / TPB, TPB>>>(mpts, mnrm, mpos, mrot, spos, snrm);

    render_kernel<<<NBLOCKS, TPB>>>(sources, mpos,
                                    cyl_p1, cyl_p2, cyl_r,
                                    box_p1, box_p2,
                                    snrm, img);
}